// round 6
// baseline (speedup 1.0000x reference)
#include <cuda_runtime.h>

#define BB   512
#define SS   500
#define DIN  14
#define HH   128
#define NN   256
#define LS4  4
#define LRES 6
#define MM   (BB*SS)   // 256000 rows

typedef unsigned long long ull;

// ---------------- scratch (device globals; no allocation allowed) ----------------
__device__ float g_h [BB*SS*HH];       // residual stream
__device__ float g_z [BB*SS*HH];       // LN output
__device__ float g_t [BB*SS*2*HH];     // conv out / MLP hidden
__device__ float g_K [LS4*SS*HH];      // S4 conv kernels, layout [L][S][H]
__device__ float g_te[BB*HH];          // time embedding

// ---------------- helpers ----------------
__device__ __forceinline__ float gelu_f(float x){
    return 0.5f*x*(1.0f + erff(x*0.70710678118654752f));
}
__device__ __forceinline__ ull pack2(float x, float y){
    ull d; asm("mov.b64 %0, {%1, %2};" : "=l"(d) : "f"(x), "f"(y)); return d;
}
__device__ __forceinline__ void unpack2(ull v, float& x, float& y){
    asm("mov.b64 {%0, %1}, %2;" : "=f"(x), "=f"(y) : "l"(v));
}
__device__ __forceinline__ ull fma2(ull a, ull b, ull c){
    ull d;
    asm("fma.rn.f32x2 %0, %1, %2, %3;" : "=l"(d) : "l"(a), "l"(b), "l"(c));
    return d;
}

// ---------------- S4 kernel materialization: K[l][s][h] = 2*Re sum_n C_n w_n^s --------
__global__ __launch_bounds__(512)
void s4k_kernel(const float* __restrict__ logA, const float* __restrict__ Aim,
                const float* __restrict__ Cre,  const float* __restrict__ Cim,
                const float* __restrict__ logdt, float* __restrict__ Kout)
{
    int lh  = blockIdx.x;          // l*HH + h
    int l   = lh / HH, h = lh % HH;
    int tid = threadIdx.x;
    __shared__ float2 sW[9][NN];   // w^(2^k)
    __shared__ float2 sC[NN];
    if (tid < NN){
        int n = tid;
        float dt  = expf(logdt[lh]);
        int  idx  = lh*NN + n;
        float are = -expf(logA[idx]);
        float aim = Aim[idx];
        float dre = dt*are, dim = dt*aim;
        float er  = expf(dre);
        float si, co; sincosf(dim, &si, &co);
        float wre = er*co, wim = er*si;
        // C = (Cre + i Cim) * (w - 1) / A
        float nre = wre - 1.f, nim = wim;
        float inv = 1.f/(are*are + aim*aim);
        float qre = (nre*are + nim*aim)*inv;
        float qim = (nim*are - nre*aim)*inv;
        float c0 = Cre[idx], c1 = Cim[idx];
        sC[n] = make_float2(c0*qre - c1*qim, c0*qim + c1*qre);
        float pr = wre, pi = wim;
        #pragma unroll
        for (int k=0;k<9;k++){
            sW[k][n] = make_float2(pr, pi);
            float t = pr*pr - pi*pi;
            pi = 2.f*pr*pi;
            pr = t;
        }
    }
    __syncthreads();
    int s = tid;
    if (s < SS){
        float acc = 0.f;
        for (int n=0;n<NN;n++){
            float pr = 1.f, pi = 0.f;
            #pragma unroll
            for (int k=0;k<9;k++){
                float2 w = sW[k][n];
                bool bit = (s>>k)&1;
                float wx = bit ? w.x : 1.f;
                float wy = bit ? w.y : 0.f;
                float t = pr*wx - pi*wy;
                pi = pr*wy + pi*wx;
                pr = t;
            }
            float2 c = sC[n];
            acc = fmaf(c.x, pr, acc);
            acc = fmaf(-c.y, pi, acc);
        }
        Kout[((long long)l*SS + s)*HH + h] = 2.f*acc;   // [L][S][H] layout
    }
}

// ---------------- input embedding: h = (x*mask+obs)@W_in + b_in + pe*mask -------------
__global__ __launch_bounds__(128)
void embed_kernel(const float* __restrict__ x, const float* __restrict__ mask,
                  const float* __restrict__ obs, const float* __restrict__ Win,
                  const float* __restrict__ bin, float* __restrict__ out)
{
    int row = blockIdx.x;          // b*SS + s
    int s   = row % SS;
    int j   = threadIdx.x;
    __shared__ float xc[DIN];
    __shared__ float smk;
    if (j < DIN) xc[j] = x[row*DIN + j]*mask[row] + obs[row*DIN + j];
    if (j == 0)  smk = mask[row];
    __syncthreads();
    float acc = bin[j];
    #pragma unroll
    for (int k=0;k<DIN;k++) acc = fmaf(xc[k], Win[k*HH + j], acc);
    float pe;
    if (j < 64){
        float d = expf(-9.2103403719761836f * (2.0f*j) * (1.0f/128.0f));
        pe = sinf((float)s * d);
    } else {
        int jj = j - 64;
        float d = expf(-9.2103403719761836f * (2.0f*jj) * (1.0f/128.0f));
        pe = cosf((float)s * d);
    }
    out[(long long)row*HH + j] = acc + pe*smk;
}

// ---------------- LayerNorm (one warp per 128-float row) ----------------
__global__ __launch_bounds__(256)
void ln_kernel(const float* __restrict__ in, const float* __restrict__ g,
               const float* __restrict__ bta, float* __restrict__ out)
{
    int warp = threadIdx.x >> 5, lane = threadIdx.x & 31;
    long long row = (long long)blockIdx.x*8 + warp;
    const float4* in4 = (const float4*)(in + row*HH);
    float4 v = in4[lane];
    float s = v.x+v.y+v.z+v.w;
    float q = v.x*v.x + v.y*v.y + v.z*v.z + v.w*v.w;
    #pragma unroll
    for (int o=16;o>0;o>>=1){
        s += __shfl_xor_sync(0xffffffffu, s, o);
        q += __shfl_xor_sync(0xffffffffu, q, o);
    }
    float m   = s*(1.0f/HH);
    float var = q*(1.0f/HH) - m*m;
    float rs  = rsqrtf(var + 1e-5f);
    float4 gg = ((const float4*)g)[lane];
    float4 bb = ((const float4*)bta)[lane];
    float4 o4;
    o4.x = (v.x-m)*rs*gg.x + bb.x;
    o4.y = (v.y-m)*rs*gg.y + bb.y;
    o4.z = (v.z-m)*rs*gg.z + bb.z;
    o4.w = (v.w-m)*rs*gg.w + bb.w;
    ((float4*)(out + row*HH))[lane] = o4;
}

// ---------------- causal depthwise conv + D*u + GELU, h-pair vectorized ---------------
// Thread t handles channels (2t, 2t+1) as an f32x2 lane pair. All operands are
// natural float2 loads: no duplication movs, no overlapping K pairs.
__global__ __launch_bounds__(64)
void conv_kernel(const float* __restrict__ z, const float* __restrict__ Kf,
                 const float* __restrict__ D, float* __restrict__ out)
{
    int b  = blockIdx.y;
    int s0 = blockIdx.x * 16;
    int t  = threadIdx.x;           // h-pair index, 0..63
    __shared__ ull zsh[16][64];     // z tile as h-pairs

    const ull* z2 = (const ull*)(z + (long long)b*SS*HH);   // [S][64]
    const ull* K2 = (const ull*)Kf;                          // [S][64]

    ull acc[16];
    #pragma unroll
    for (int i=0;i<16;i++) acc[i] = 0ULL;

    for (int t0 = 0; t0 <= s0; t0 += 16){
        __syncthreads();
        #pragma unroll
        for (int j=0;j<16;j++){
            int tt = t0 + j;
            zsh[j][t] = (tt < SS) ? z2[tt*64 + t] : 0ULL;
        }
        __syncthreads();
        int base = s0 - t0 - 15;    // lag d = base + m
        ull Kr[31];
        #pragma unroll
        for (int m=0;m<31;m++){
            int d = base + m;
            Kr[m] = (d >= 0 && d < SS) ? K2[d*64 + t] : 0ULL;
        }
        #pragma unroll
        for (int j=0;j<16;j++){
            ull zv = zsh[j][t];
            #pragma unroll
            for (int i=0;i<16;i++)
                acc[i] = fma2(Kr[15 + i - j], zv, acc[i]);
        }
    }

    float2 D2 = ((const float2*)D)[t];
    ull* out2 = (ull*)(out + (long long)b*SS*HH);
    #pragma unroll
    for (int i=0;i<16;i++){
        int s = s0 + i;
        if (s < SS){
            float a0, a1; unpack2(acc[i], a0, a1);
            float u0, u1; unpack2(z2[s*64 + t], u0, u1);
            float y0 = gelu_f(a0 + D2.x*u0);
            float y1 = gelu_f(a1 + D2.y*u1);
            out2[s*64 + t] = pack2(y0, y1);
        }
    }
}

// ---------------- SGEMM: C = act(A@W + bias) [+ res] ----------------
// 128x128 block tile, 128 threads, 8(M)x16(N) per thread -> 0.75 B/MAC smem traffic.
template<int ACT, bool RES>
__device__ __forceinline__ void store_row16(float* __restrict__ C, const float* __restrict__ res,
        int N, long long m, int c0, const float v[16], const float4* bq)
{
    #pragma unroll
    for (int q=0;q<4;q++){
        float4 o = make_float4(v[q*4+0]+bq[q].x, v[q*4+1]+bq[q].y,
                               v[q*4+2]+bq[q].z, v[q*4+3]+bq[q].w);
        if (ACT == 1){
            o.x=gelu_f(o.x); o.y=gelu_f(o.y); o.z=gelu_f(o.z); o.w=gelu_f(o.w);
        }
        if (RES){
            float4 r = *(const float4*)&res[m*N + c0 + q*4];
            o.x+=r.x; o.y+=r.y; o.z+=r.z; o.w+=r.w;
        }
        *(float4*)&C[m*N + c0 + q*4] = o;
    }
}

template<int ACT, bool RES>
__global__ __launch_bounds__(128)
void gemm_kernel(const float* __restrict__ A, const float* __restrict__ W,
                 const float* __restrict__ bias, const float* __restrict__ res,
                 float* __restrict__ C, int N, int K)
{
    __shared__ float As[8][132];
    __shared__ float Bs[8][132];
    int tid = threadIdx.x;
    int m0 = blockIdx.x * 128;
    int n0 = blockIdx.y * 128;
    int tx = tid & 7, ty = tid >> 3;     // tx: 8 n-groups of 16, ty: 16 m-groups of 8

    // loaders: A row = tid (128 rows x 8 k), B: 8 k-rows x 128 n
    const float* Aptr = A + ((long long)m0 + tid)*K;
    int brow = tid >> 4, bcq = tid & 15;
    const float* Bptr = W + brow*N + n0 + bcq*4;

    ull acc[4][16];
    #pragma unroll
    for (int i=0;i<4;i++)
        #pragma unroll
        for (int j=0;j<16;j++) acc[i][j] = 0ULL;

    int KT = K >> 3;
    float4 Ar0 = *(const float4*)(Aptr);
    float4 Ar1 = *(const float4*)(Aptr + 4);
    float4 Br0 = *(const float4*)(Bptr);
    float4 Br1 = *(const float4*)(Bptr + 64);

    for (int kt=0; kt<KT; kt++){
        As[0][tid]=Ar0.x; As[1][tid]=Ar0.y; As[2][tid]=Ar0.z; As[3][tid]=Ar0.w;
        As[4][tid]=Ar1.x; As[5][tid]=Ar1.y; As[6][tid]=Ar1.z; As[7][tid]=Ar1.w;
        *(float4*)&Bs[brow][bcq*4]      = Br0;
        *(float4*)&Bs[brow][bcq*4 + 64] = Br1;
        __syncthreads();
        if (kt+1 < KT){
            Ar0 = *(const float4*)(Aptr + (kt+1)*8);
            Ar1 = *(const float4*)(Aptr + (kt+1)*8 + 4);
            Br0 = *(const float4*)(Bptr + (kt+1)*8*N);
            Br1 = *(const float4*)(Bptr + (kt+1)*8*N + 64);
        }
        #pragma unroll
        for (int k=0;k<8;k++){
            float4 a0 = *(const float4*)&As[k][ty*8];
            float4 a1 = *(const float4*)&As[k][ty*8+4];
            ull ap[4] = { pack2(a0.x,a0.y), pack2(a0.z,a0.w),
                          pack2(a1.x,a1.y), pack2(a1.z,a1.w) };
            #pragma unroll
            for (int q=0;q<4;q++){
                float4 bv = *(const float4*)&Bs[k][tx*16 + q*4];
                ull b0 = pack2(bv.x,bv.x);
                ull b1 = pack2(bv.y,bv.y);
                ull b2 = pack2(bv.z,bv.z);
                ull b3 = pack2(bv.w,bv.w);
                #pragma unroll
                for (int i=0;i<4;i++){
                    acc[i][q*4+0] = fma2(ap[i], b0, acc[i][q*4+0]);
                    acc[i][q*4+1] = fma2(ap[i], b1, acc[i][q*4+1]);
                    acc[i][q*4+2] = fma2(ap[i], b2, acc[i][q*4+2]);
                    acc[i][q*4+3] = fma2(ap[i], b3, acc[i][q*4+3]);
                }
            }
        }
        __syncthreads();
    }

    int c0 = n0 + tx*16;
    float4 bq[4];
    #pragma unroll
    for (int q=0;q<4;q++) bq[q] = *(const float4*)&bias[c0 + q*4];
    #pragma unroll
    for (int i=0;i<4;i++){
        float lo[16], hi[16];
        #pragma unroll
        for (int j=0;j<16;j++) unpack2(acc[i][j], lo[j], hi[j]);
        long long mrow = m0 + ty*8 + i*2;
        store_row16<ACT,RES>(C, res, N, mrow,   c0, lo, bq);
        store_row16<ACT,RES>(C, res, N, mrow+1, c0, hi, bq);
    }
}

// ---------------- diffusion time embedding MLP ----------------
__global__ __launch_bounds__(256)
void time_kernel(const int* __restrict__ ts, const float* __restrict__ W1, const float* __restrict__ b1,
                 const float* __restrict__ W2, const float* __restrict__ b2, float* __restrict__ te)
{
    int b = blockIdx.x, j = threadIdx.x;
    __shared__ float s0[256], s1[256];
    float t = (float)ts[b];
    const float emb = 9.2103403719761836f / 127.0f;
    if (j < 128) s0[j] = sinf(t * expf(-emb * (float)j));
    else         s0[j] = cosf(t * expf(-emb * (float)(j-128)));
    __syncthreads();
    float acc = b1[j];
    for (int k=0;k<256;k++) acc = fmaf(s0[k], W1[k*256 + j], acc);
    s1[j] = acc / (1.f + expf(-acc));   // silu
    __syncthreads();
    if (j < 128){
        float a2 = b2[j];
        for (int k=0;k<256;k++) a2 = fmaf(s1[k], W2[k*128 + j], a2);
        te[b*HH + j] = a2;
    }
}

// ---------------- h += te[b] broadcast ----------------
__global__ __launch_bounds__(256)
void addte_kernel(float* __restrict__ h, const float* __restrict__ te)
{
    long long i = (long long)blockIdx.x*blockDim.x + threadIdx.x;  // float4 index
    float4* h4 = (float4*)h;
    const float4* te4 = (const float4*)te;
    int col = (int)(i & 31);
    long long row = i >> 5;
    int b = (int)(row / SS);
    float4 v = h4[i], tv = te4[b*32 + col];
    v.x += tv.x; v.y += tv.y; v.z += tv.z; v.w += tv.w;
    h4[i] = v;
}

// ---------------- output projection 128 -> 14 ----------------
__global__ __launch_bounds__(256)
void outproj_kernel(const float* __restrict__ h, const float* __restrict__ Wo,
                    const float* __restrict__ bo, float* __restrict__ out)
{
    __shared__ float hs[16][129];
    __shared__ float ws[DIN][132];
    int tid = threadIdx.x;
    long long row0 = (long long)blockIdx.x * 16;
    for (int idx = tid; idx < HH*DIN; idx += 256){
        int hh = idx / DIN, d = idx % DIN;
        ws[d][hh] = Wo[idx];
    }
    for (int idx = tid; idx < 16*HH; idx += 256){
        int r = idx >> 7, c = idx & 127;
        hs[r][c] = h[(row0 + r)*HH + c];
    }
    __syncthreads();
    if (tid < 16*DIN){
        int r = tid / DIN, d = tid % DIN;
        float acc = bo[d];
        #pragma unroll 8
        for (int k=0;k<HH;k++) acc = fmaf(hs[r][k], ws[d][k], acc);
        out[(row0 + r)*DIN + d] = acc;
    }
}

// ---------------- launcher ----------------
extern "C" void kernel_launch(void* const* d_in, const int* in_sizes, int n_in,
                              void* d_out, int out_size)
{
    const float* x       = (const float*)d_in[0];
    const int*   tsteps  = (const int*)  d_in[1];
    const float* mask    = (const float*)d_in[2];
    const float* obs     = (const float*)d_in[3];
    const float* W_in    = (const float*)d_in[4];
    const float* b_in    = (const float*)d_in[5];
    const float* tW1     = (const float*)d_in[6];
    const float* tb1     = (const float*)d_in[7];
    const float* tW2     = (const float*)d_in[8];
    const float* tb2     = (const float*)d_in[9];
    const float* s4_ln_g = (const float*)d_in[10];
    const float* s4_ln_b = (const float*)d_in[11];
    const float* s4_logA = (const float*)d_in[12];
    const float* s4_Aim  = (const float*)d_in[13];
    const float* s4_Cre  = (const float*)d_in[14];
    const float* s4_Cim  = (const float*)d_in[15];
    const float* s4_D    = (const float*)d_in[16];
    const float* s4_logdt= (const float*)d_in[17];
    const float* s4_Wo   = (const float*)d_in[18];
    const float* s4_bo   = (const float*)d_in[19];
    const float* r_ln_g  = (const float*)d_in[20];
    const float* r_ln_b  = (const float*)d_in[21];
    const float* r_W1    = (const float*)d_in[22];
    const float* r_b1    = (const float*)d_in[23];
    const float* r_W2    = (const float*)d_in[24];
    const float* r_b2    = (const float*)d_in[25];
    const float* W_out   = (const float*)d_in[26];
    const float* b_out   = (const float*)d_in[27];
    float* out = (float*)d_out;

    float *ph, *pz, *pt, *pK, *pte;
    cudaGetSymbolAddress((void**)&ph,  g_h);
    cudaGetSymbolAddress((void**)&pz,  g_z);
    cudaGetSymbolAddress((void**)&pt,  g_t);
    cudaGetSymbolAddress((void**)&pK,  g_K);
    cudaGetSymbolAddress((void**)&pte, g_te);

    // S4 kernels for all 4 layers
    s4k_kernel<<<LS4*HH, 512>>>(s4_logA, s4_Aim, s4_Cre, s4_Cim, s4_logdt, pK);

    // input embedding
    embed_kernel<<<MM, 128>>>(x, mask, obs, W_in, b_in, ph);

    // S4D layers
    for (int l = 0; l < LS4; l++){
        ln_kernel<<<MM/8, 256>>>(ph, s4_ln_g + l*HH, s4_ln_b + l*HH, pz);
        conv_kernel<<<dim3(32, BB), 64>>>(pz, pK + (long long)l*SS*HH, s4_D + l*HH, pt);
        gemm_kernel<0, true><<<dim3(MM/128, 1), 128>>>(pt, s4_Wo + l*HH*HH, s4_bo + l*HH,
                                                       ph, ph, HH, HH);
    }

    // time embedding
    time_kernel<<<BB, 256>>>(tsteps, tW1, tb1, tW2, tb2, pte);
    addte_kernel<<<(MM*HH/4)/256, 256>>>(ph, pte);

    // residual MLP blocks
    for (int l = 0; l < LRES; l++){
        ln_kernel<<<MM/8, 256>>>(ph, r_ln_g + l*HH, r_ln_b + l*HH, pz);
        gemm_kernel<1, false><<<dim3(MM/128, 2), 128>>>(pz, r_W1 + l*HH*2*HH, r_b1 + l*2*HH,
                                                        nullptr, pt, 2*HH, HH);
        gemm_kernel<0, true><<<dim3(MM/128, 1), 128>>>(pt, r_W2 + l*2*HH*HH, r_b2 + l*HH,
                                                       ph, ph, HH, 2*HH);
    }

    // output projection
    outproj_kernel<<<MM/16, 256>>>(ph, W_out, b_out, out);
}

// round 7
// speedup vs baseline: 1.5300x; 1.5300x over previous
#include <cuda_runtime.h>

#define BB   512
#define SS   500
#define DIN  14
#define HH   128
#define NN   256
#define LS4  4
#define LRES 6
#define MM   (BB*SS)   // 256000 rows

typedef unsigned long long ull;

// ---------------- scratch (device globals; no allocation allowed) ----------------
__device__ float g_h [BB*SS*HH];       // residual stream
__device__ float g_z [BB*SS*HH];       // LN output
__device__ float g_t [BB*SS*2*HH];     // conv out / MLP hidden
__device__ float g_K [LS4*SS*HH];      // S4 conv kernels, layout [L][S][H]
__device__ float g_te[BB*HH];          // time embedding

// ---------------- helpers ----------------
__device__ __forceinline__ float gelu_f(float x){
    return 0.5f*x*(1.0f + erff(x*0.70710678118654752f));
}
__device__ __forceinline__ ull pack2(float x, float y){
    ull d; asm("mov.b64 %0, {%1, %2};" : "=l"(d) : "f"(x), "f"(y)); return d;
}
__device__ __forceinline__ void unpack2(ull v, float& x, float& y){
    asm("mov.b64 {%0, %1}, %2;" : "=f"(x), "=f"(y) : "l"(v));
}
__device__ __forceinline__ ull fma2(ull a, ull b, ull c){
    ull d;
    asm("fma.rn.f32x2 %0, %1, %2, %3;" : "=l"(d) : "l"(a), "l"(b), "l"(c));
    return d;
}

// ---------------- S4 kernel materialization: K[l][s][h] = 2*Re sum_n C_n w_n^s --------
__global__ __launch_bounds__(512)
void s4k_kernel(const float* __restrict__ logA, const float* __restrict__ Aim,
                const float* __restrict__ Cre,  const float* __restrict__ Cim,
                const float* __restrict__ logdt, float* __restrict__ Kout)
{
    int lh  = blockIdx.x;          // l*HH + h
    int l   = lh / HH, h = lh % HH;
    int tid = threadIdx.x;
    __shared__ float2 sW[9][NN];   // w^(2^k)
    __shared__ float2 sC[NN];
    if (tid < NN){
        int n = tid;
        float dt  = expf(logdt[lh]);
        int  idx  = lh*NN + n;
        float are = -expf(logA[idx]);
        float aim = Aim[idx];
        float dre = dt*are, dim = dt*aim;
        float er  = expf(dre);
        float si, co; sincosf(dim, &si, &co);
        float wre = er*co, wim = er*si;
        // C = (Cre + i Cim) * (w - 1) / A
        float nre = wre - 1.f, nim = wim;
        float inv = 1.f/(are*are + aim*aim);
        float qre = (nre*are + nim*aim)*inv;
        float qim = (nim*are - nre*aim)*inv;
        float c0 = Cre[idx], c1 = Cim[idx];
        sC[n] = make_float2(c0*qre - c1*qim, c0*qim + c1*qre);
        float pr = wre, pi = wim;
        #pragma unroll
        for (int k=0;k<9;k++){
            sW[k][n] = make_float2(pr, pi);
            float t = pr*pr - pi*pi;
            pi = 2.f*pr*pi;
            pr = t;
        }
    }
    __syncthreads();
    int s = tid;
    if (s < SS){
        float acc = 0.f;
        for (int n=0;n<NN;n++){
            float pr = 1.f, pi = 0.f;
            #pragma unroll
            for (int k=0;k<9;k++){
                float2 w = sW[k][n];
                bool bit = (s>>k)&1;
                float wx = bit ? w.x : 1.f;
                float wy = bit ? w.y : 0.f;
                float t = pr*wx - pi*wy;
                pi = pr*wy + pi*wx;
                pr = t;
            }
            float2 c = sC[n];
            acc = fmaf(c.x, pr, acc);
            acc = fmaf(-c.y, pi, acc);
        }
        Kout[((long long)l*SS + s)*HH + h] = 2.f*acc;   // [L][S][H] layout
    }
}

// ---------------- input embedding: h = (x*mask+obs)@W_in + b_in + pe*mask -------------
__global__ __launch_bounds__(128)
void embed_kernel(const float* __restrict__ x, const float* __restrict__ mask,
                  const float* __restrict__ obs, const float* __restrict__ Win,
                  const float* __restrict__ bin, float* __restrict__ out)
{
    int row = blockIdx.x;          // b*SS + s
    int s   = row % SS;
    int j   = threadIdx.x;
    __shared__ float xc[DIN];
    __shared__ float smk;
    if (j < DIN) xc[j] = x[row*DIN + j]*mask[row] + obs[row*DIN + j];
    if (j == 0)  smk = mask[row];
    __syncthreads();
    float acc = bin[j];
    #pragma unroll
    for (int k=0;k<DIN;k++) acc = fmaf(xc[k], Win[k*HH + j], acc);
    float pe;
    if (j < 64){
        float d = expf(-9.2103403719761836f * (2.0f*j) * (1.0f/128.0f));
        pe = sinf((float)s * d);
    } else {
        int jj = j - 64;
        float d = expf(-9.2103403719761836f * (2.0f*jj) * (1.0f/128.0f));
        pe = cosf((float)s * d);
    }
    out[(long long)row*HH + j] = acc + pe*smk;
}

// ---------------- LayerNorm (one warp per 128-float row) ----------------
__global__ __launch_bounds__(256)
void ln_kernel(const float* __restrict__ in, const float* __restrict__ g,
               const float* __restrict__ bta, float* __restrict__ out)
{
    int warp = threadIdx.x >> 5, lane = threadIdx.x & 31;
    long long row = (long long)blockIdx.x*8 + warp;
    const float4* in4 = (const float4*)(in + row*HH);
    float4 v = in4[lane];
    float s = v.x+v.y+v.z+v.w;
    float q = v.x*v.x + v.y*v.y + v.z*v.z + v.w*v.w;
    #pragma unroll
    for (int o=16;o>0;o>>=1){
        s += __shfl_xor_sync(0xffffffffu, s, o);
        q += __shfl_xor_sync(0xffffffffu, q, o);
    }
    float m   = s*(1.0f/HH);
    float var = q*(1.0f/HH) - m*m;
    float rs  = rsqrtf(var + 1e-5f);
    float4 gg = ((const float4*)g)[lane];
    float4 bb = ((const float4*)bta)[lane];
    float4 o4;
    o4.x = (v.x-m)*rs*gg.x + bb.x;
    o4.y = (v.y-m)*rs*gg.y + bb.y;
    o4.z = (v.z-m)*rs*gg.z + bb.z;
    o4.w = (v.w-m)*rs*gg.w + bb.w;
    ((float4*)(out + row*HH))[lane] = o4;
}

// ---------------- causal depthwise conv + D*u + GELU, h-pair vectorized ---------------
// Thread t handles channels (2t, 2t+1) as an f32x2 lane pair. All operands are
// natural float2 loads: no duplication movs, no overlapping K pairs.
__global__ __launch_bounds__(64)
void conv_kernel(const float* __restrict__ z, const float* __restrict__ Kf,
                 const float* __restrict__ D, float* __restrict__ out)
{
    int b  = blockIdx.y;
    int s0 = blockIdx.x * 16;
    int t  = threadIdx.x;           // h-pair index, 0..63
    __shared__ ull zsh[16][64];     // z tile as h-pairs

    const ull* z2 = (const ull*)(z + (long long)b*SS*HH);   // [S][64]
    const ull* K2 = (const ull*)Kf;                          // [S][64]

    ull acc[16];
    #pragma unroll
    for (int i=0;i<16;i++) acc[i] = 0ULL;

    for (int t0 = 0; t0 <= s0; t0 += 16){
        __syncthreads();
        #pragma unroll
        for (int j=0;j<16;j++){
            int tt = t0 + j;
            zsh[j][t] = (tt < SS) ? z2[tt*64 + t] : 0ULL;
        }
        __syncthreads();
        int base = s0 - t0 - 15;    // lag d = base + m
        ull Kr[31];
        #pragma unroll
        for (int m=0;m<31;m++){
            int d = base + m;
            Kr[m] = (d >= 0 && d < SS) ? K2[d*64 + t] : 0ULL;
        }
        #pragma unroll
        for (int j=0;j<16;j++){
            ull zv = zsh[j][t];
            #pragma unroll
            for (int i=0;i<16;i++)
                acc[i] = fma2(Kr[15 + i - j], zv, acc[i]);
        }
    }

    float2 D2 = ((const float2*)D)[t];
    ull* out2 = (ull*)(out + (long long)b*SS*HH);
    #pragma unroll
    for (int i=0;i<16;i++){
        int s = s0 + i;
        if (s < SS){
            float a0, a1; unpack2(acc[i], a0, a1);
            float u0, u1; unpack2(z2[s*64 + t], u0, u1);
            float y0 = gelu_f(a0 + D2.x*u0);
            float y1 = gelu_f(a1 + D2.y*u1);
            out2[s*64 + t] = pack2(y0, y1);
        }
    }
}

// ---------------- SGEMM: C = act(A@W + bias) [+ res], f32x2 inner (R2 version) -------
template<int ACT, bool RES>
__device__ __forceinline__ void store_row(float* __restrict__ C, const float* __restrict__ res,
        int N, long long m, int c0, int c1, const float v[8], float4 bl, float4 bh)
{
    float4 lo = make_float4(v[0]+bl.x, v[1]+bl.y, v[2]+bl.z, v[3]+bl.w);
    float4 hi = make_float4(v[4]+bh.x, v[5]+bh.y, v[6]+bh.z, v[7]+bh.w);
    if (ACT == 1){
        lo.x=gelu_f(lo.x); lo.y=gelu_f(lo.y); lo.z=gelu_f(lo.z); lo.w=gelu_f(lo.w);
        hi.x=gelu_f(hi.x); hi.y=gelu_f(hi.y); hi.z=gelu_f(hi.z); hi.w=gelu_f(hi.w);
    }
    if (RES){
        float4 r0 = *(const float4*)&res[m*N + c0];
        float4 r1 = *(const float4*)&res[m*N + c1];
        lo.x+=r0.x; lo.y+=r0.y; lo.z+=r0.z; lo.w+=r0.w;
        hi.x+=r1.x; hi.y+=r1.y; hi.z+=r1.z; hi.w+=r1.w;
    }
    *(float4*)&C[m*N + c0] = lo;
    *(float4*)&C[m*N + c1] = hi;
}

template<int ACT, bool RES>
__global__ __launch_bounds__(256, 2)
void gemm_kernel(const float* __restrict__ A, const float* __restrict__ W,
                 const float* __restrict__ bias, const float* __restrict__ res,
                 float* __restrict__ C, int N, int K)
{
    __shared__ float As[8][132];
    __shared__ float Bs[8][132];
    int tid = threadIdx.x;
    int m0 = blockIdx.x * 128;
    int n0 = blockIdx.y * 128;
    int tx = tid & 15, ty = tid >> 4;

    int arow = tid >> 1, akq = tid & 1;   // A: 128 rows x 8k  -> 256 float4
    int brow = tid >> 5, bnq = tid & 31;  // B: 8k x 128 cols  -> 256 float4
    const float* Aptr = A + ((long long)m0 + arow)*K + akq*4;
    const float* Bptr = W + brow*N + n0 + bnq*4;

    ull acc[4][8];
    #pragma unroll
    for (int i=0;i<4;i++)
        #pragma unroll
        for (int j=0;j<8;j++) acc[i][j] = 0ULL;

    int KT = K >> 3;
    float4 Ar = *(const float4*)Aptr;
    float4 Br = *(const float4*)Bptr;
    for (int kt=0; kt<KT; kt++){
        As[akq*4+0][arow] = Ar.x;
        As[akq*4+1][arow] = Ar.y;
        As[akq*4+2][arow] = Ar.z;
        As[akq*4+3][arow] = Ar.w;
        *(float4*)&Bs[brow][bnq*4] = Br;
        __syncthreads();
        if (kt+1 < KT){
            Ar = *(const float4*)(Aptr + (kt+1)*8);
            Br = *(const float4*)(Bptr + (kt+1)*8*N);
        }
        #pragma unroll
        for (int k=0;k<8;k++){
            float4 a0 = *(const float4*)&As[k][ty*8];
            float4 a1 = *(const float4*)&As[k][ty*8+4];
            float4 b0 = *(const float4*)&Bs[k][tx*4];
            float4 b1 = *(const float4*)&Bs[k][64 + tx*4];
            ull ap[4] = { pack2(a0.x,a0.y), pack2(a0.z,a0.w),
                          pack2(a1.x,a1.y), pack2(a1.z,a1.w) };
            ull bb[8] = { pack2(b0.x,b0.x), pack2(b0.y,b0.y),
                          pack2(b0.z,b0.z), pack2(b0.w,b0.w),
                          pack2(b1.x,b1.x), pack2(b1.y,b1.y),
                          pack2(b1.z,b1.z), pack2(b1.w,b1.w) };
            #pragma unroll
            for (int i=0;i<4;i++)
                #pragma unroll
                for (int j=0;j<8;j++)
                    acc[i][j] = fma2(ap[i], bb[j], acc[i][j]);
        }
        __syncthreads();
    }

    int c0 = n0 + tx*4, c1 = n0 + 64 + tx*4;
    float4 bl = *(const float4*)&bias[c0];
    float4 bh = *(const float4*)&bias[c1];
    #pragma unroll
    for (int i=0;i<4;i++){
        float e[8], o[8];
        #pragma unroll
        for (int j=0;j<8;j++) unpack2(acc[i][j], e[j], o[j]);
        long long mrow = m0 + ty*8 + i*2;
        store_row<ACT,RES>(C, res, N, mrow,   c0, c1, e, bl, bh);
        store_row<ACT,RES>(C, res, N, mrow+1, c0, c1, o, bl, bh);
    }
}

// ---------------- diffusion time embedding MLP ----------------
__global__ __launch_bounds__(256)
void time_kernel(const int* __restrict__ ts, const float* __restrict__ W1, const float* __restrict__ b1,
                 const float* __restrict__ W2, const float* __restrict__ b2, float* __restrict__ te)
{
    int b = blockIdx.x, j = threadIdx.x;
    __shared__ float s0[256], s1[256];
    float t = (float)ts[b];
    const float emb = 9.2103403719761836f / 127.0f;
    if (j < 128) s0[j] = sinf(t * expf(-emb * (float)j));
    else         s0[j] = cosf(t * expf(-emb * (float)(j-128)));
    __syncthreads();
    float acc = b1[j];
    for (int k=0;k<256;k++) acc = fmaf(s0[k], W1[k*256 + j], acc);
    s1[j] = acc / (1.f + expf(-acc));   // silu
    __syncthreads();
    if (j < 128){
        float a2 = b2[j];
        for (int k=0;k<256;k++) a2 = fmaf(s1[k], W2[k*128 + j], a2);
        te[b*HH + j] = a2;
    }
}

// ---------------- h += te[b] broadcast ----------------
__global__ __launch_bounds__(256)
void addte_kernel(float* __restrict__ h, const float* __restrict__ te)
{
    long long i = (long long)blockIdx.x*blockDim.x + threadIdx.x;  // float4 index
    float4* h4 = (float4*)h;
    const float4* te4 = (const float4*)te;
    int col = (int)(i & 31);
    long long row = i >> 5;
    int b = (int)(row / SS);
    float4 v = h4[i], tv = te4[b*32 + col];
    v.x += tv.x; v.y += tv.y; v.z += tv.z; v.w += tv.w;
    h4[i] = v;
}

// ---------------- output projection 128 -> 14 ----------------
__global__ __launch_bounds__(256)
void outproj_kernel(const float* __restrict__ h, const float* __restrict__ Wo,
                    const float* __restrict__ bo, float* __restrict__ out)
{
    __shared__ float hs[16][129];
    __shared__ float ws[DIN][132];
    int tid = threadIdx.x;
    long long row0 = (long long)blockIdx.x * 16;
    for (int idx = tid; idx < HH*DIN; idx += 256){
        int hh = idx / DIN, d = idx % DIN;
        ws[d][hh] = Wo[idx];
    }
    for (int idx = tid; idx < 16*HH; idx += 256){
        int r = idx >> 7, c = idx & 127;
        hs[r][c] = h[(row0 + r)*HH + c];
    }
    __syncthreads();
    if (tid < 16*DIN){
        int r = tid / DIN, d = tid % DIN;
        float acc = bo[d];
        #pragma unroll 8
        for (int k=0;k<HH;k++) acc = fmaf(hs[r][k], ws[d][k], acc);
        out[(row0 + r)*DIN + d] = acc;
    }
}

// ---------------- launcher ----------------
extern "C" void kernel_launch(void* const* d_in, const int* in_sizes, int n_in,
                              void* d_out, int out_size)
{
    const float* x       = (const float*)d_in[0];
    const int*   tsteps  = (const int*)  d_in[1];
    const float* mask    = (const float*)d_in[2];
    const float* obs     = (const float*)d_in[3];
    const float* W_in    = (const float*)d_in[4];
    const float* b_in    = (const float*)d_in[5];
    const float* tW1     = (const float*)d_in[6];
    const float* tb1     = (const float*)d_in[7];
    const float* tW2     = (const float*)d_in[8];
    const float* tb2     = (const float*)d_in[9];
    const float* s4_ln_g = (const float*)d_in[10];
    const float* s4_ln_b = (const float*)d_in[11];
    const float* s4_logA = (const float*)d_in[12];
    const float* s4_Aim  = (const float*)d_in[13];
    const float* s4_Cre  = (const float*)d_in[14];
    const float* s4_Cim  = (const float*)d_in[15];
    const float* s4_D    = (const float*)d_in[16];
    const float* s4_logdt= (const float*)d_in[17];
    const float* s4_Wo   = (const float*)d_in[18];
    const float* s4_bo   = (const float*)d_in[19];
    const float* r_ln_g  = (const float*)d_in[20];
    const float* r_ln_b  = (const float*)d_in[21];
    const float* r_W1    = (const float*)d_in[22];
    const float* r_b1    = (const float*)d_in[23];
    const float* r_W2    = (const float*)d_in[24];
    const float* r_b2    = (const float*)d_in[25];
    const float* W_out   = (const float*)d_in[26];
    const float* b_out   = (const float*)d_in[27];
    float* out = (float*)d_out;

    float *ph, *pz, *pt, *pK, *pte;
    cudaGetSymbolAddress((void**)&ph,  g_h);
    cudaGetSymbolAddress((void**)&pz,  g_z);
    cudaGetSymbolAddress((void**)&pt,  g_t);
    cudaGetSymbolAddress((void**)&pK,  g_K);
    cudaGetSymbolAddress((void**)&pte, g_te);

    // S4 kernels for all 4 layers
    s4k_kernel<<<LS4*HH, 512>>>(s4_logA, s4_Aim, s4_Cre, s4_Cim, s4_logdt, pK);

    // input embedding
    embed_kernel<<<MM, 128>>>(x, mask, obs, W_in, b_in, ph);

    // S4D layers
    for (int l = 0; l < LS4; l++){
        ln_kernel<<<MM/8, 256>>>(ph, s4_ln_g + l*HH, s4_ln_b + l*HH, pz);
        conv_kernel<<<dim3(32, BB), 64>>>(pz, pK + (long long)l*SS*HH, s4_D + l*HH, pt);
        gemm_kernel<0, true><<<dim3(MM/128, 1), 256>>>(pt, s4_Wo + l*HH*HH, s4_bo + l*HH,
                                                       ph, ph, HH, HH);
    }

    // time embedding
    time_kernel<<<BB, 256>>>(tsteps, tW1, tb1, tW2, tb2, pte);
    addte_kernel<<<(MM*HH/4)/256, 256>>>(ph, pte);

    // residual MLP blocks
    for (int l = 0; l < LRES; l++){
        ln_kernel<<<MM/8, 256>>>(ph, r_ln_g + l*HH, r_ln_b + l*HH, pz);
        gemm_kernel<1, false><<<dim3(MM/128, 2), 256>>>(pz, r_W1 + l*HH*2*HH, r_b1 + l*2*HH,
                                                        nullptr, pt, 2*HH, HH);
        gemm_kernel<0, true><<<dim3(MM/128, 1), 256>>>(pt, r_W2 + l*2*HH*HH, r_b2 + l*HH,
                                                       ph, ph, HH, 2*HH);
    }

    // output projection
    outproj_kernel<<<MM/16, 256>>>(ph, W_out, b_out, out);
}